// round 14
// baseline (speedup 1.0000x reference)
#include <cuda_runtime.h>

// Problem constants (from reference): N=32, RES=256, C=2, K=1024, T=1, EPS=1e-6
#define NB   32
#define RESO 256
#define KP   1024
#define EPSF 1e-6f
#define C1F  1.4426950408889634f          // log2(e)/T
#define UF   (C1F * C1F)                  // folded scale on squared distances
#define LN2F 0.6931471805599453f

// Scratch (no allocations allowed) --------------------------------------------
__device__ float g_part[1024];          // per-block weighted loss partials
__device__ float g_cnt [1024];          // per-block visibility counts
__device__ int   g_ctr = 0;             // last-block counter (self-resetting)

// MUFU intrinsics -------------------------------------------------------------
__device__ __forceinline__ float lg2a(float x) { float y; asm("lg2.approx.f32 %0, %1;" : "=f"(y) : "f"(x)); return y; }
__device__ __forceinline__ float ex2_neg(float x) {
    float y; asm("{ .reg .f32 t; neg.f32 t, %1; ex2.approx.f32 %0, t; }" : "=f"(y) : "f"(x)); return y;
}
__device__ __forceinline__ float sqrt_abs(float x) {
    float y; asm("{ .reg .f32 t; abs.f32 t, %1; sqrt.approx.f32 %0, t; }" : "=f"(y) : "f"(x)); return y;
}

// Packed f32x2 helpers --------------------------------------------------------
typedef unsigned long long u64;
__device__ __forceinline__ u64 pack2(float v) {
    u64 r; asm("mov.b64 %0, {%1, %1};" : "=l"(r) : "f"(v)); return r;
}
__device__ __forceinline__ u64 add2(u64 a, u64 b) {
    u64 r; asm("add.rn.f32x2 %0, %1, %2;" : "=l"(r) : "l"(a), "l"(b)); return r;
}
__device__ __forceinline__ u64 fma2(u64 a, u64 b, u64 c) {
    u64 r; asm("fma.rn.f32x2 %0, %1, %2, %3;" : "=l"(r) : "l"(a), "l"(b), "l"(c)); return r;
}
__device__ __forceinline__ void unpack2(u64 p, float& lo, float& hi) {
    asm("mov.b64 {%0, %1}, %2;" : "=f"(lo), "=f"(hi) : "l"(p));
}

// Single fused kernel: sampling + pairwise CE + weighted reduction ------------
// 1 warp = 4 consecutive j's. Block = 8 warps = 32 j's. Grid = 32*32 = 1024.
// Each block samples its batch's full src set into smem (corner-parallel) and
// its own 32 trg points; 32-way cross-block redundancy of src sampling is
// L2-resident and cheaper than a separate kernel + graph-node gap.
__global__ __launch_bounds__(256) void fused_kernel(
        const float* __restrict__ sflow, const float* __restrict__ tflow,
        const float* __restrict__ skp,  const float* __restrict__ tkp,
        const int* __restrict__ vis, const float* __restrict__ wt,
        float* __restrict__ out) {
    __shared__ float shx[KP], shy[KP], shp[KP];            // src SoA for batch n (12 KB)
    __shared__ float sh_l[8], sh_v[8];
    __shared__ bool  s_last;
    const int warp = threadIdx.x >> 5, lane = threadIdx.x & 31;
    const int n     = blockIdx.x >> 5;                     // 32 blocks per batch
    const int jbase = ((blockIdx.x & 31) << 5) + (warp << 2);

    // ---- trg gathers issue FIRST (latency hidden under src sampling) --------
    float tax = 0.f, tay = 0.f;
    if (lane < 16) {
        int q = lane >> 2, c = lane & 3;
        float2 p = ((const float2*)tkp)[n * KP + jbase + q];
        float x0f = floorf(p.x), y0f = floorf(p.y);
        float wx = p.x - x0f, wy = p.y - y0f;
        int dx = c & 1, dy = c >> 1;
        int xi = (int)x0f + dx, yi = (int)y0f + dy;
        if (xi >= 0 && xi < RESO && yi >= 0 && yi < RESO) {
            float w = (dx ? wx : 1.f - wx) * (dy ? wy : 1.f - wy);
            const float2 v = *(const float2*)(tflow + ((((size_t)n * RESO + yi) * RESO + xi) << 1));
            tax = v.x * w;
            tay = v.y * w;
        }
    }

    // ---- src sampling into smem: 1024 points x 4 corners / 256 threads ------
#pragma unroll 4
    for (int r = 0; r < 16; r++) {
        int t  = (r << 8) + threadIdx.x;                   // [0, 4096)
        int pt = t >> 2, c = t & 3;
        float2 p = ((const float2*)skp)[n * KP + pt];
        float x0f = floorf(p.x), y0f = floorf(p.y);
        float wx = p.x - x0f, wy = p.y - y0f;
        int dx = c & 1, dy = c >> 1;
        int xi = (int)x0f + dx, yi = (int)y0f + dy;
        float ax = 0.f, ay = 0.f;
        if (xi >= 0 && xi < RESO && yi >= 0 && yi < RESO) {
            float w = (dx ? wx : 1.f - wx) * (dy ? wy : 1.f - wy);
            const float2 v = *(const float2*)(sflow + ((((size_t)n * RESO + yi) * RESO + xi) << 1));
            ax = v.x * w;
            ay = v.y * w;
        }
        ax += __shfl_xor_sync(0xffffffffu, ax, 1);
        ay += __shfl_xor_sync(0xffffffffu, ay, 1);
        ax += __shfl_xor_sync(0xffffffffu, ax, 2);
        ay += __shfl_xor_sync(0xffffffffu, ay, 2);
        if (c == 0) {
            float sx = ax + EPSF, sy = ay + EPSF;          // fold +eps into src side
            shx[pt] = sx;
            shy[pt] = sy;
            shp[pt] = UF * fmaf(sx, sx, sy * sy);          // u*|s|^2
        }
    }

    // ---- combine trg corners, broadcast, build per-j constants --------------
    tax += __shfl_xor_sync(0xffffffffu, tax, 1);
    tay += __shfl_xor_sync(0xffffffffu, tay, 1);
    tax += __shfl_xor_sync(0xffffffffu, tax, 2);
    tay += __shfl_xor_sync(0xffffffffu, tay, 2);
    u64 qx2[4], qy2[4], rr2[4];
    float qxs[4], qys[4], rrs[4];
#pragma unroll
    for (int q = 0; q < 4; q++) {
        float txq = __shfl_sync(0xffffffffu, tax, q << 2);
        float tyq = __shfl_sync(0xffffffffu, tay, q << 2);
        qxs[q] = -2.f * UF * txq;
        qys[q] = -2.f * UF * tyq;
        rrs[q] = UF * fmaf(txq, txq, tyq * tyq);
        qx2[q] = pack2(qxs[q]);
        qy2[q] = pack2(qys[q]);
        rr2[q] = pack2(rrs[q]);
    }
    __syncthreads();

    // ---- round-9 inner loop (measured-best): scalar MUFU exp ----------------
    float a0 = 0.f, a1 = 0.f, a2 = 0.f, a3 = 0.f;
    const u64* px = (const u64*)shx;                       // consecutive-i packed pairs
    const u64* py = (const u64*)shy;
    const u64* pp = (const u64*)shp;
#pragma unroll 4
    for (int it = 0; it < KP / 2; it += 32) {
        int pi = it + lane;
        u64 x2 = px[pi], y2 = py[pi], p2 = pp[pi];
        {   u64 d = fma2(x2, qx2[0], fma2(y2, qy2[0], add2(p2, rr2[0])));
            float lo, hi; unpack2(d, lo, hi);
            a0 += ex2_neg(sqrt_abs(lo));
            a0 += ex2_neg(sqrt_abs(hi)); }
        {   u64 d = fma2(x2, qx2[1], fma2(y2, qy2[1], add2(p2, rr2[1])));
            float lo, hi; unpack2(d, lo, hi);
            a1 += ex2_neg(sqrt_abs(lo));
            a1 += ex2_neg(sqrt_abs(hi)); }
        {   u64 d = fma2(x2, qx2[2], fma2(y2, qy2[2], add2(p2, rr2[2])));
            float lo, hi; unpack2(d, lo, hi);
            a2 += ex2_neg(sqrt_abs(lo));
            a2 += ex2_neg(sqrt_abs(hi)); }
        {   u64 d = fma2(x2, qx2[3], fma2(y2, qy2[3], add2(p2, rr2[3])));
            float lo, hi; unpack2(d, lo, hi);
            a3 += ex2_neg(sqrt_abs(lo));
            a3 += ex2_neg(sqrt_abs(hi)); }
    }
#pragma unroll
    for (int o = 16; o; o >>= 1) {
        a0 += __shfl_xor_sync(0xffffffffu, a0, o);
        a1 += __shfl_xor_sync(0xffffffffu, a1, o);
        a2 += __shfl_xor_sync(0xffffffffu, a2, o);
        a3 += __shfl_xor_sync(0xffffffffu, a3, o);
    }

    if (lane == 0) {
        float acc[4] = {a0, a1, a2, a3};
        float lsum = 0.f, vsum = 0.f;
#pragma unroll
        for (int q = 0; q < 4; q++) {
            int j = jbase + q;
            // scaled diagonal: v_jj = C1 * dist_jj (same dot form)
            float dsq = fmaf(shx[j], qxs[q], fmaf(shy[j], qys[q], shp[j] + rrs[q]));
            float vjj = sqrt_abs(dsq);
            // loss = 2*(ln(acc) + dist_jj) = 2*ln2*(lg2(acc) + v_jj)
            float loss = (2.f * LN2F) * (lg2a(acc[q]) + vjj);
            float vi = vis[n * KP + j] ? 1.f : 0.f;
            lsum = fmaf(loss * wt[n * KP + j], vi, lsum);
            vsum += vi;
        }
        sh_l[warp] = lsum; sh_v[warp] = vsum;
    }
    __syncthreads();

    if (threadIdx.x == 0) {
        float l = 0.f, v = 0.f;
#pragma unroll
        for (int w = 0; w < 8; w++) { l += sh_l[w]; v += sh_v[w]; }
        g_part[blockIdx.x] = l;
        g_cnt [blockIdx.x] = v;
        __threadfence();
        int prev = atomicAdd(&g_ctr, 1);
        s_last = (prev == 1023);
    }
    __syncthreads();

    // Last block performs the final deterministic fixed-tree reduce.
    if (s_last) {
        __shared__ float fl[8], fv[8];
        float l = 0.f, v = 0.f;
#pragma unroll
        for (int r = 0; r < 4; r++) {
            int i = threadIdx.x + (r << 8);
            l += g_part[i];
            v += g_cnt [i];
        }
#pragma unroll
        for (int o = 16; o; o >>= 1) {
            l += __shfl_xor_sync(0xffffffffu, l, o);
            v += __shfl_xor_sync(0xffffffffu, v, o);
        }
        if (lane == 0) { fl[warp] = l; fv[warp] = v; }
        __syncthreads();
        if (threadIdx.x == 0) {
            l = 0.f; v = 0.f;
#pragma unroll
            for (int w = 0; w < 8; w++) { l += fl[w]; v += fv[w]; }
            out[0] = l / v;
            g_ctr = 0;                                     // reset for next graph replay
        }
    }
}

extern "C" void kernel_launch(void* const* d_in, const int* in_sizes, int n_in,
                              void* d_out, int out_size) {
    const float* sflow = (const float*)d_in[0];
    const float* tflow = (const float*)d_in[1];
    const float* skp   = (const float*)d_in[2];
    const float* tkp   = (const float*)d_in[3];
    const int*   vis   = (const int*)d_in[4];   // bool serialized as int32
    const float* wt    = (const float*)d_in[5];
    float*       out   = (float*)d_out;

    fused_kernel<<<1024, 256>>>(sflow, tflow, skp, tkp, vis, wt, out);
}

// round 15
// speedup vs baseline: 1.3667x; 1.3667x over previous
#include <cuda_runtime.h>
#include <cstdint>

// Problem constants (from reference): N=32, RES=256, C=2, K=1024, T=1, EPS=1e-6
#define NB   32
#define RESO 256
#define KP   1024
#define EPSF 1e-6f
#define C1F  1.4426950408889634f          // log2(e)/T
#define UF   (C1F * C1F)                  // folded scale on squared distances
#define LN2F 0.6931471805599453f

// Scratch (no allocations allowed) --------------------------------------------
__device__ float g_sx[NB * KP];         // src.x + eps
__device__ float g_sy[NB * KP];         // src.y + eps
__device__ float g_sp[NB * KP];         // u * |src|^2
__device__ float g_tx[NB * KP];         // trg.x
__device__ float g_ty[NB * KP];         // trg.y
__device__ float g_part[1024];          // per-block weighted loss partials
__device__ float g_cnt [1024];          // per-block visibility counts
__device__ int   g_ctr = 0;             // last-block counter (self-resetting)

// MUFU intrinsics -------------------------------------------------------------
__device__ __forceinline__ float lg2a(float x) { float y; asm("lg2.approx.f32 %0, %1;" : "=f"(y) : "f"(x)); return y; }
__device__ __forceinline__ float sqrt_abs(float x) {
    float y; asm("{ .reg .f32 t; abs.f32 t, %1; sqrt.approx.f32 %0, t; }" : "=f"(y) : "f"(x)); return y;
}
// Two exponentials in ONE MUFU op: e = 2^(h.lo), 2^(h.hi) in f16x2
__device__ __forceinline__ uint32_t ex2_h2(uint32_t h) {
    uint32_t e; asm("ex2.approx.f16x2 %0, %1;" : "=r"(e) : "r"(h)); return e;
}
__device__ __forceinline__ uint32_t pack_h2(float hi, float lo) {   // d.hi=hi, d.lo=lo
    uint32_t h; asm("cvt.rn.f16x2.f32 %0, %1, %2;" : "=r"(h) : "f"(hi), "f"(lo)); return h;
}
__device__ __forceinline__ void unpack_h2(uint32_t e, float& lo, float& hi) {
    asm("{ .reg .b16 l, u; mov.b32 {l, u}, %2; cvt.f32.f16 %0, l; cvt.f32.f16 %1, u; }"
        : "=f"(lo), "=f"(hi) : "r"(e));
}

// Packed f32x2 helpers --------------------------------------------------------
typedef unsigned long long u64;
__device__ __forceinline__ u64 pack2(float v) {
    u64 r; asm("mov.b64 %0, {%1, %1};" : "=l"(r) : "f"(v)); return r;
}
__device__ __forceinline__ u64 add2(u64 a, u64 b) {
    u64 r; asm("add.rn.f32x2 %0, %1, %2;" : "=l"(r) : "l"(a), "l"(b)); return r;
}
__device__ __forceinline__ u64 fma2(u64 a, u64 b, u64 c) {
    u64 r; asm("fma.rn.f32x2 %0, %1, %2, %3;" : "=l"(r) : "l"(a), "l"(b), "l"(c)); return r;
}
__device__ __forceinline__ void unpack2(u64 p, float& lo, float& hi) {
    asm("mov.b64 {%0, %1}, %2;" : "=f"(lo), "=f"(hi) : "l"(p));
}

// Kernel 1: corner-parallel bilinear sampling (SoA outputs, src+trg) ----------
__global__ __launch_bounds__(256) void sample_kernel(
        const float* __restrict__ sflow, const float* __restrict__ tflow,
        const float* __restrict__ skp,  const float* __restrict__ tkp) {
    int g      = blockIdx.x * blockDim.x + threadIdx.x;    // [0, 262144)
    int samp   = g >> 2;                                   // [0, 2*N*K)
    int corner = g & 3;                                    // dx = c&1, dy = c>>1
    int k      = samp & (NB * KP - 1);                     // n*K + kp
    int n      = k >> 10;
    bool is_src = samp < NB * KP;

    const float* kp   = is_src ? skp   : tkp;
    const float* flow = is_src ? sflow : tflow;
    float2 p = ((const float2*)kp)[k];

    float x0f = floorf(p.x), y0f = floorf(p.y);
    float wx  = p.x - x0f,   wy  = p.y - y0f;
    int dx = corner & 1, dy = corner >> 1;
    int xi = (int)x0f + dx, yi = (int)y0f + dy;
    float w = (dx ? wx : 1.f - wx) * (dy ? wy : 1.f - wy);

    float ax = 0.f, ay = 0.f;
    if (xi >= 0 && xi < RESO && yi >= 0 && yi < RESO) {
        const float2 v = *(const float2*)(flow + ((((size_t)n * RESO + yi) * RESO + xi) << 1));
        ax = v.x * w;
        ay = v.y * w;
    }
    ax += __shfl_xor_sync(0xffffffffu, ax, 1);
    ay += __shfl_xor_sync(0xffffffffu, ay, 1);
    ax += __shfl_xor_sync(0xffffffffu, ax, 2);
    ay += __shfl_xor_sync(0xffffffffu, ay, 2);

    if (corner == 0) {
        if (is_src) {
            float sx = ax + EPSF, sy = ay + EPSF;          // fold +eps into src side
            g_sx[k] = sx;
            g_sy[k] = sy;
            g_sp[k] = UF * fmaf(sx, sx, sy * sy);          // u*|s|^2
        } else {
            g_tx[k] = ax;
            g_ty[k] = ay;
        }
    }
}

// Kernel 2: pairwise + CE diag + fused reduction ------------------------------
// exp pairs computed with ONE ex2.approx.f16x2 per packed (2-pair) unit:
// MUFU per 8 pair-ops drops from 16 to 12 instrs. sqrt stays f32.
// 1 warp = 4 j's, block = 8 warps = 32 j's, grid = 1024.
__global__ __launch_bounds__(256) void pair_kernel(const int* __restrict__ vis,
                                                   const float* __restrict__ wt,
                                                   float* __restrict__ out) {
    __shared__ float shx[KP], shy[KP], shp[KP];            // src SoA for batch n (12 KB)
    __shared__ float sh_l[8], sh_v[8];
    __shared__ bool  s_last;
    const int warp = threadIdx.x >> 5, lane = threadIdx.x & 31;
    const int n     = blockIdx.x >> 5;                     // 32 blocks per batch
    const int jbase = ((blockIdx.x & 31) << 5) + (warp << 2);

    {   // vectorized smem fill: 256 float4 per array
        const float4* gx = (const float4*)(g_sx + n * KP);
        const float4* gy = (const float4*)(g_sy + n * KP);
        const float4* gp = (const float4*)(g_sp + n * KP);
        ((float4*)shx)[threadIdx.x] = gx[threadIdx.x];
        ((float4*)shy)[threadIdx.x] = gy[threadIdx.x];
        ((float4*)shp)[threadIdx.x] = gp[threadIdx.x];
    }
    __syncthreads();

    // per-j constants
    u64 qx2[4], qy2[4], rr2[4];
    float qxs[4], qys[4], rrs[4];
#pragma unroll
    for (int q = 0; q < 4; q++) {
        float txq = g_tx[n * KP + jbase + q];
        float tyq = g_ty[n * KP + jbase + q];
        qxs[q] = -2.f * UF * txq;
        qys[q] = -2.f * UF * tyq;
        rrs[q] = UF * fmaf(txq, txq, tyq * tyq);
        qx2[q] = pack2(qxs[q]);
        qy2[q] = pack2(qys[q]);
        rr2[q] = pack2(rrs[q]);
    }

    float a0 = 0.f, a1 = 0.f, a2 = 0.f, a3 = 0.f;
    const u64* px = (const u64*)shx;                       // consecutive-i packed pairs
    const u64* py = (const u64*)shy;
    const u64* pp = (const u64*)shp;
#pragma unroll 4
    for (int it = 0; it < KP / 2; it += 32) {
        int pi = it + lane;
        u64 x2 = px[pi], y2 = py[pi], p2 = pp[pi];
        {   u64 d = fma2(x2, qx2[0], fma2(y2, qy2[0], add2(p2, rr2[0])));
            float lo, hi; unpack2(d, lo, hi);
            uint32_t h = pack_h2(sqrt_abs(hi), sqrt_abs(lo)) ^ 0x80008000u;  // -t pair
            float elo, ehi; unpack_h2(ex2_h2(h), elo, ehi);                  // 1 MUFU, 2 exps
            a0 += elo; a0 += ehi; }
        {   u64 d = fma2(x2, qx2[1], fma2(y2, qy2[1], add2(p2, rr2[1])));
            float lo, hi; unpack2(d, lo, hi);
            uint32_t h = pack_h2(sqrt_abs(hi), sqrt_abs(lo)) ^ 0x80008000u;
            float elo, ehi; unpack_h2(ex2_h2(h), elo, ehi);
            a1 += elo; a1 += ehi; }
        {   u64 d = fma2(x2, qx2[2], fma2(y2, qy2[2], add2(p2, rr2[2])));
            float lo, hi; unpack2(d, lo, hi);
            uint32_t h = pack_h2(sqrt_abs(hi), sqrt_abs(lo)) ^ 0x80008000u;
            float elo, ehi; unpack_h2(ex2_h2(h), elo, ehi);
            a2 += elo; a2 += ehi; }
        {   u64 d = fma2(x2, qx2[3], fma2(y2, qy2[3], add2(p2, rr2[3])));
            float lo, hi; unpack2(d, lo, hi);
            uint32_t h = pack_h2(sqrt_abs(hi), sqrt_abs(lo)) ^ 0x80008000u;
            float elo, ehi; unpack_h2(ex2_h2(h), elo, ehi);
            a3 += elo; a3 += ehi; }
    }
#pragma unroll
    for (int o = 16; o; o >>= 1) {
        a0 += __shfl_xor_sync(0xffffffffu, a0, o);
        a1 += __shfl_xor_sync(0xffffffffu, a1, o);
        a2 += __shfl_xor_sync(0xffffffffu, a2, o);
        a3 += __shfl_xor_sync(0xffffffffu, a3, o);
    }

    if (lane == 0) {
        float acc[4] = {a0, a1, a2, a3};
        float lsum = 0.f, vsum = 0.f;
#pragma unroll
        for (int q = 0; q < 4; q++) {
            int j = jbase + q;
            // scaled diagonal in full f32: v_jj = C1 * dist_jj (same dot form)
            float dsq = fmaf(shx[j], qxs[q], fmaf(shy[j], qys[q], shp[j] + rrs[q]));
            float vjj = sqrt_abs(dsq);
            // loss = 2*(ln(acc) + dist_jj) = 2*ln2*(lg2(acc) + v_jj)
            float loss = (2.f * LN2F) * (lg2a(acc[q]) + vjj);
            float vi = vis[n * KP + j] ? 1.f : 0.f;
            lsum = fmaf(loss * wt[n * KP + j], vi, lsum);
            vsum += vi;
        }
        sh_l[warp] = lsum; sh_v[warp] = vsum;
    }
    __syncthreads();

    if (threadIdx.x == 0) {
        float l = 0.f, v = 0.f;
#pragma unroll
        for (int w = 0; w < 8; w++) { l += sh_l[w]; v += sh_v[w]; }
        g_part[blockIdx.x] = l;
        g_cnt [blockIdx.x] = v;
        __threadfence();
        int prev = atomicAdd(&g_ctr, 1);
        s_last = (prev == 1023);
    }
    __syncthreads();

    // Last block performs the final deterministic fixed-tree reduce.
    if (s_last) {
        __shared__ float fl[8], fv[8];
        float l = 0.f, v = 0.f;
#pragma unroll
        for (int r = 0; r < 4; r++) {
            int i = threadIdx.x + (r << 8);
            l += g_part[i];
            v += g_cnt [i];
        }
#pragma unroll
        for (int o = 16; o; o >>= 1) {
            l += __shfl_xor_sync(0xffffffffu, l, o);
            v += __shfl_xor_sync(0xffffffffu, v, o);
        }
        if (lane == 0) { fl[warp] = l; fv[warp] = v; }
        __syncthreads();
        if (threadIdx.x == 0) {
            l = 0.f; v = 0.f;
#pragma unroll
            for (int w = 0; w < 8; w++) { l += fl[w]; v += fv[w]; }
            out[0] = l / v;
            g_ctr = 0;                                     // reset for next graph replay
        }
    }
}

extern "C" void kernel_launch(void* const* d_in, const int* in_sizes, int n_in,
                              void* d_out, int out_size) {
    const float* sflow = (const float*)d_in[0];
    const float* tflow = (const float*)d_in[1];
    const float* skp   = (const float*)d_in[2];
    const float* tkp   = (const float*)d_in[3];
    const int*   vis   = (const int*)d_in[4];   // bool serialized as int32
    const float* wt    = (const float*)d_in[5];
    float*       out   = (float*)d_out;

    sample_kernel<<<(2 * NB * KP * 4) / 256, 256>>>(sflow, tflow, skp, tkp);
    pair_kernel<<<1024, 256>>>(vis, wt, out);
}